// round 3
// baseline (speedup 1.0000x reference)
#include <cuda_runtime.h>
#include <cstdint>

// Problem constants
#define NF 8
#define NK 16
#define NY 16
#define NX 16
#define NP 32
#define NT 8
#define NB 64
#define VOL (NY*NX*NP*NT)       // 65536 per (b,f)
#define COLS (NY*NX*NP)         // 8192 (y,x,p) points per (b,f)
#define CHUNKS 8
#define PTS (COLS/CHUNKS)       // 1024 points per chunk
#define JITER (PTS/256)         // 4 mainloop iterations
#define YXC (PTS/NP)            // 32 yx per chunk

// Precomputed tables (device globals — no allocation allowed)
__device__ float g_klat[NF*NK*NY];
__device__ float g_klon[NF*NK*NX];
__device__ float g_klev[NF*NK*NP];
__device__ float g_r[NF*NK];        // geometric ratio exp(-1/tau)
__device__ float g_integr[NF*NK];   // integrated (accumulated atomically)

using u64 = unsigned long long;

// Packed f32x2 helpers (B300 packed fp32 pipe)
__device__ __forceinline__ u64 pk2(float lo, float hi) {
    u64 r; asm("mov.b64 %0,{%1,%2};" : "=l"(r) : "f"(lo), "f"(hi)); return r;
}
__device__ __forceinline__ u64 fma2(u64 a, u64 b, u64 c) {
    u64 d; asm("fma.rn.f32x2 %0,%1,%2,%3;" : "=l"(d) : "l"(a), "l"(b), "l"(c)); return d;
}
__device__ __forceinline__ u64 mul2(u64 a, u64 b) {
    u64 d; asm("mul.rn.f32x2 %0,%1,%2;" : "=l"(d) : "l"(a), "l"(b)); return d;
}
__device__ __forceinline__ float2 up2(u64 a) {
    float2 v; asm("mov.b64 {%0,%1},%2;" : "=f"(v.x), "=f"(v.y) : "l"(a)); return v;
}

// cp.async helpers
__device__ __forceinline__ void cp16(void* dst_smem, const void* src) {
    uint32_t d = (uint32_t)__cvta_generic_to_shared(dst_smem);
    asm volatile("cp.async.ca.shared.global [%0],[%1],16;" :: "r"(d), "l"(src));
}
__device__ __forceinline__ void cp_commit() {
    asm volatile("cp.async.commit_group;");
}
template<int N> __device__ __forceinline__ void cp_wait() {
    asm volatile("cp.async.wait_group %0;" :: "n"(N));
}

// ---------------------------------------------------------------------------
// Zero kernel: clears g_integr and out (feat/prep accumulate atomically).
// ---------------------------------------------------------------------------
__global__ void zero_kernel(float* __restrict__ out) {
    int i = blockIdx.x * 256 + threadIdx.x;
    if (i < NF*NK) g_integr[i] = 0.f;
    if (i < NB*NF*NK) out[i] = 0.f;
}

// ---------------------------------------------------------------------------
// Prep kernel: 4 CTAs per (f,k) (512 CTAs). Builds 1D tables + ratio r
// (sub-CTA 0 writes them), and accumulates partial integrated sums.
// ---------------------------------------------------------------------------
__global__ __launch_bounds__(256)
void prep_kernel(const float* __restrict__ qw,
                 const float* __restrict__ mu_lat, const float* __restrict__ ls_lat,
                 const float* __restrict__ mu_lon, const float* __restrict__ ls_lon,
                 const float* __restrict__ mu_lev, const float* __restrict__ ls_lev,
                 const float* __restrict__ lt_time)
{
    const int bid = blockIdx.x;
    const int fk  = bid >> 2;
    const int sub = bid & 3;
    const int tid = threadIdx.x;
    __shared__ float s_lat[NY], s_lon[NX], s_lev[NP];
    __shared__ float s_part[8];

    if (tid < NY) {
        float c = -1.f + 2.f * (float)tid / (float)(NY - 1);
        float z = (c - mu_lat[fk]) / expf(ls_lat[fk]);
        float v = expf(-0.5f * z * z);
        s_lat[tid] = v;
        if (sub == 0) g_klat[fk*NY + tid] = v;
    } else if (tid < 32) {
        int x = tid - 16;
        float c = -1.f + 2.f * (float)x / (float)(NX - 1);
        float z = (c - mu_lon[fk]) / expf(ls_lon[fk]);
        float v = expf(-0.5f * z * z);
        s_lon[x] = v;
        if (sub == 0) g_klon[fk*NX + x] = v;
    } else if (tid < 64) {
        int p = tid - 32;
        float c = -1.f + 2.f * (float)p / (float)(NP - 1);
        float z = (c - mu_lev[fk]) / expf(ls_lev[fk]);
        float v = expf(-0.5f * z * z);
        s_lev[p] = v;
        if (sub == 0) g_klev[fk*NP + p] = v;
    }
    float tau = expf(lt_time[fk]) + 1e-6f;
    float r = expf(-1.f / tau);
    if (sub == 0 && tid == 0) g_r[fk] = r;
    __syncthreads();

    // Partial integrated over this sub-chunk (2048 of 8192 points)
    const float4* q4 = (const float4*)qw;
    float local = 0.f;
    #pragma unroll 2
    for (int it = 0; it < 8; ++it) {
        int idx = sub*2048 + it*256 + tid;  // point index
        float4 q0 = q4[idx*2];
        float4 q1 = q4[idx*2 + 1];
        float s = q1.w;
        s = fmaf(s, r, q1.z); s = fmaf(s, r, q1.y); s = fmaf(s, r, q1.x);
        s = fmaf(s, r, q0.w); s = fmaf(s, r, q0.z); s = fmaf(s, r, q0.y);
        s = fmaf(s, r, q0.x);
        int p = idx & 31, x = (idx >> 5) & 15, y = idx >> 9;
        local += s * (s_lat[y] * s_lon[x] * s_lev[p]);
    }
    #pragma unroll
    for (int o = 16; o; o >>= 1) local += __shfl_xor_sync(0xffffffffu, local, o);
    if ((tid & 31) == 0) s_part[tid >> 5] = local;
    __syncthreads();
    if (tid == 0) {
        float s = 0.f;
        #pragma unroll
        for (int w = 0; w < 8; ++w) s += s_part[w];
        atomicAdd(&g_integr[fk], s);
    }
}

// ---------------------------------------------------------------------------
// Main kernel: grid = NB*NF*CHUNKS (4096 CTAs, 256 threads).
// cp.async double-buffered staging of patch+qw into shared; each thread
// copies exactly the 64 bytes it later reads -> no barriers in mainloop.
// Thread layout: p = tid & 31 constant per thread -> klev in epilogue.
// Inner math: packed Horner over t (geometric ktime) for 8 k-pairs.
// ---------------------------------------------------------------------------
__global__ __launch_bounds__(256, 4)
void feat_kernel(const float* __restrict__ patch,
                 const float* __restrict__ qw,
                 float* __restrict__ out)
{
    const int bid   = blockIdx.x;
    const int bf    = bid & (NB*NF - 1);
    const int chunk = bid >> 9;
    const int f     = bf & (NF - 1);
    const int tid   = threadIdx.x;

    __shared__ __align__(16) float s_cl[YXC*NK];     // 2 KB
    __shared__ float4 sb_p[2][2][256];               // 16 KB patch staging
    __shared__ float4 sb_q[2][2][256];               // 16 KB qw staging
    __shared__ float s_red[8*NK];

    const float4* pb = (const float4*)(patch + (size_t)bf * VOL)
                       + (size_t)chunk * (PTS*2);
    const float4* qb = (const float4*)qw + (size_t)chunk * (PTS*2);

    // Stage buffer 0 (j=0) immediately
    cp16(&sb_p[0][0][tid], pb + tid*2);
    cp16(&sb_p[0][1][tid], pb + tid*2 + 1);
    cp16(&sb_q[0][0][tid], qb + tid*2);
    cp16(&sb_q[0][1][tid], qb + tid*2 + 1);
    cp_commit();

    // Combined lat*lon table for this f, this chunk's yx range
    for (int i = tid; i < YXC*NK; i += 256) {
        int k  = i & 15;
        int yx = chunk*YXC + (i >> 4);
        s_cl[i] = g_klat[(f*NK + k)*NY + (yx >> 4)] * g_klon[(f*NK + k)*NX + (yx & 15)];
    }

    u64 r2[8], acc[8];
    #pragma unroll
    for (int kp = 0; kp < 8; ++kp) {
        int k0 = f*NK + 2*kp;
        r2[kp]  = pk2(g_r[k0], g_r[k0+1]);
        acc[kp] = 0ull;
    }
    __syncthreads();   // s_cl visible

    #pragma unroll
    for (int j = 0; j < JITER; ++j) {
        // Stage next buffer
        if (j + 1 < JITER) {
            int iln = (j+1)*256 + tid;
            int nb = (j+1) & 1;
            cp16(&sb_p[nb][0][tid], pb + iln*2);
            cp16(&sb_p[nb][1][tid], pb + iln*2 + 1);
            cp16(&sb_q[nb][0][tid], qb + iln*2);
            cp16(&sb_q[nb][1][tid], qb + iln*2 + 1);
        }
        cp_commit();
        cp_wait<1>();   // buffer j ready (per-thread: we read only our own slots)

        const int buf = j & 1;
        float4 a0 = sb_p[buf][0][tid];
        float4 a1 = sb_p[buf][1][tid];
        float4 q0 = sb_q[buf][0][tid];
        float4 q1 = sb_q[buf][1][tid];

        float wp0 = a0.x*q0.x, wp1 = a0.y*q0.y, wp2 = a0.z*q0.z, wp3 = a0.w*q0.w;
        float wp4 = a1.x*q1.x, wp5 = a1.y*q1.y, wp6 = a1.z*q1.z, wp7 = a1.w*q1.w;
        u64 w[8];
        w[0] = pk2(wp0, wp0); w[1] = pk2(wp1, wp1);
        w[2] = pk2(wp2, wp2); w[3] = pk2(wp3, wp3);
        w[4] = pk2(wp4, wp4); w[5] = pk2(wp5, wp5);
        w[6] = pk2(wp6, wp6); w[7] = pk2(wp7, wp7);

        const int il = j*256 + tid;
        const u64* cl = (const u64*)(s_cl + (il >> 5) * NK);  // warp-uniform

        #pragma unroll
        for (int kp = 0; kp < 8; ++kp) {
            u64 s = w[7];
            #pragma unroll
            for (int t = 6; t >= 0; --t) s = fma2(s, r2[kp], w[t]);
            acc[kp] = fma2(s, cl[kp], acc[kp]);
        }
    }

    // Epilogue: apply klev (per-thread p), reduce 256 -> 1 per k, scale,
    // atomically accumulate into out.
    const int p = tid & 31;
    float v[16];
    #pragma unroll
    for (int kp = 0; kp < 8; ++kp) {
        int k0 = f*NK + 2*kp;
        u64 kv2 = pk2(g_klev[k0*NP + p], g_klev[(k0+1)*NP + p]);
        float2 t2 = up2(mul2(acc[kp], kv2));
        v[2*kp]   = t2.x;
        v[2*kp+1] = t2.y;
    }
    #pragma unroll
    for (int kk = 0; kk < 16; ++kk) {
        #pragma unroll
        for (int o = 16; o; o >>= 1) v[kk] += __shfl_xor_sync(0xffffffffu, v[kk], o);
    }
    const int lane = tid & 31, wrp = tid >> 5;
    if (lane == 0) {
        #pragma unroll
        for (int kk = 0; kk < 16; ++kk) s_red[wrp*NK + kk] = v[kk];
    }
    __syncthreads();
    if (tid < NK) {
        float s = 0.f;
        #pragma unroll
        for (int w8 = 0; w8 < 8; ++w8) s += s_red[w8*NK + tid];
        float rinv = 1.f / (g_integr[f*NK + tid] + 1e-4f);
        atomicAdd(&out[(size_t)(bf >> 3) * (NF*NK) + f*NK + tid], s * rinv);
    }
}

// ---------------------------------------------------------------------------
// Launch. Inputs (metadata order): patch, quadweights, mu_lat, logsigma_lat,
// mu_lon, logsigma_lon, mu_lev, logsigma_lev, logtau_time.
// ---------------------------------------------------------------------------
extern "C" void kernel_launch(void* const* d_in, const int* in_sizes, int n_in,
                              void* d_out, int out_size)
{
    (void)in_sizes; (void)n_in; (void)out_size;
    const float* patch  = (const float*)d_in[0];
    const float* qw     = (const float*)d_in[1];
    const float* mu_lat = (const float*)d_in[2];
    const float* ls_lat = (const float*)d_in[3];
    const float* mu_lon = (const float*)d_in[4];
    const float* ls_lon = (const float*)d_in[5];
    const float* mu_lev = (const float*)d_in[6];
    const float* ls_lev = (const float*)d_in[7];
    const float* lt     = (const float*)d_in[8];
    float* out = (float*)d_out;

    zero_kernel<<<32, 256>>>(out);
    prep_kernel<<<NF*NK*4, 256>>>(qw, mu_lat, ls_lat, mu_lon, ls_lon,
                                  mu_lev, ls_lev, lt);
    feat_kernel<<<NB*NF*CHUNKS, 256>>>(patch, qw, out);
}

// round 4
// speedup vs baseline: 1.3148x; 1.3148x over previous
#include <cuda_runtime.h>
#include <cstdint>

// Problem constants
#define NF 8
#define NK 16
#define NY 16
#define NX 16
#define NP 32
#define NT 8
#define NB 64
#define VOL (NY*NX*NP*NT)       // 65536 per (b,f)
#define COLS (NY*NX*NP)         // 8192 (y,x,p) points per (b,f)
#define CHUNKS 4
#define PTS (COLS/CHUNKS)       // 2048 points per chunk
#define JITER (PTS/256)         // 8 mainloop iterations
#define YXC (PTS/NP)            // 64 yx per chunk

// Precomputed tables (device globals — no allocation allowed)
__device__ float g_klat[NF*NK*NY];
__device__ float g_klon[NF*NK*NX];
__device__ float g_klev[NF*NK*NP];
__device__ float g_r[NF*NK];          // geometric ratio exp(-1/tau)
__device__ float g_ipart[NF*NK*4];    // 4 non-atomic integration partials per (f,k)

using u64 = unsigned long long;

// Packed f32x2 helpers (B300 packed fp32 pipe)
__device__ __forceinline__ u64 pk2(float lo, float hi) {
    u64 r; asm("mov.b64 %0,{%1,%2};" : "=l"(r) : "f"(lo), "f"(hi)); return r;
}
__device__ __forceinline__ u64 fma2(u64 a, u64 b, u64 c) {
    u64 d; asm("fma.rn.f32x2 %0,%1,%2,%3;" : "=l"(d) : "l"(a), "l"(b), "l"(c)); return d;
}
__device__ __forceinline__ u64 mul2(u64 a, u64 b) {
    u64 d; asm("mul.rn.f32x2 %0,%1,%2;" : "=l"(d) : "l"(a), "l"(b)); return d;
}
__device__ __forceinline__ float2 up2(u64 a) {
    float2 v; asm("mov.b64 {%0,%1},%2;" : "=f"(v.x), "=f"(v.y) : "l"(a)); return v;
}

// ---------------------------------------------------------------------------
// Prep kernel: 4 sub-CTAs per (f,k) (512 CTAs total). Builds 1D kernel
// tables + geometric ratio r (sub 0 writes them), computes a non-atomic
// partial integration sum over its quarter of the quadrature grid, and
// zeroes its slice of the output buffer (feat accumulates atomically).
// ---------------------------------------------------------------------------
__global__ __launch_bounds__(256)
void prep_kernel(const float* __restrict__ qw,
                 const float* __restrict__ mu_lat, const float* __restrict__ ls_lat,
                 const float* __restrict__ mu_lon, const float* __restrict__ ls_lon,
                 const float* __restrict__ mu_lev, const float* __restrict__ ls_lev,
                 const float* __restrict__ lt_time,
                 float* __restrict__ out)
{
    const int bid = blockIdx.x;
    const int fk  = bid >> 2;
    const int sub = bid & 3;
    const int tid = threadIdx.x;
    __shared__ float s_lat[NY], s_lon[NX], s_lev[NP];
    __shared__ float s_part[8];

    // Zero this CTA's slice of out (512 CTAs x 16 = 8192 floats)
    if (tid < 16) out[bid*16 + tid] = 0.f;

    if (tid < NY) {
        float c = -1.f + 2.f * (float)tid / (float)(NY - 1);
        float z = (c - mu_lat[fk]) / expf(ls_lat[fk]);
        float v = expf(-0.5f * z * z);
        s_lat[tid] = v;
        if (sub == 0) g_klat[fk*NY + tid] = v;
    } else if (tid < 32) {
        int x = tid - 16;
        float c = -1.f + 2.f * (float)x / (float)(NX - 1);
        float z = (c - mu_lon[fk]) / expf(ls_lon[fk]);
        float v = expf(-0.5f * z * z);
        s_lon[x] = v;
        if (sub == 0) g_klon[fk*NX + x] = v;
    } else if (tid < 64) {
        int p = tid - 32;
        float c = -1.f + 2.f * (float)p / (float)(NP - 1);
        float z = (c - mu_lev[fk]) / expf(ls_lev[fk]);
        float v = expf(-0.5f * z * z);
        s_lev[p] = v;
        if (sub == 0) g_klev[fk*NP + p] = v;
    }
    float tau = expf(lt_time[fk]) + 1e-6f;
    float r = expf(-1.f / tau);
    if (sub == 0 && tid == 0) g_r[fk] = r;
    __syncthreads();

    // Partial integration over this sub-CTA's 2048 of 8192 points
    const float4* q4 = (const float4*)qw;
    float local = 0.f;
    #pragma unroll 2
    for (int it = 0; it < 8; ++it) {
        int idx = sub*2048 + it*256 + tid;  // point index
        float4 q0 = q4[idx*2];
        float4 q1 = q4[idx*2 + 1];
        float s = q1.w;
        s = fmaf(s, r, q1.z); s = fmaf(s, r, q1.y); s = fmaf(s, r, q1.x);
        s = fmaf(s, r, q0.w); s = fmaf(s, r, q0.z); s = fmaf(s, r, q0.y);
        s = fmaf(s, r, q0.x);
        int p = idx & 31, x = (idx >> 5) & 15, y = idx >> 9;
        local += s * (s_lat[y] * s_lon[x] * s_lev[p]);
    }
    #pragma unroll
    for (int o = 16; o; o >>= 1) local += __shfl_xor_sync(0xffffffffu, local, o);
    if ((tid & 31) == 0) s_part[tid >> 5] = local;
    __syncthreads();
    if (tid == 0) {
        float s = 0.f;
        #pragma unroll
        for (int w = 0; w < 8; ++w) s += s_part[w];
        g_ipart[bid] = s;     // non-atomic partial; feat sums the 4
    }
}

// ---------------------------------------------------------------------------
// Main kernel: grid = NB*NF*CHUNKS (2048 CTAs, 256 threads, 4 CTAs/SM).
// CTA (bf, chunk) processes a contiguous quarter of the 8192 (y,x,p) points
// for one (b,f) pair and atomically accumulates scaled partials into out.
// Thread layout: p = tid & 31 constant per thread -> klev in epilogue.
// Inner math: packed Horner over t (geometric ktime) for 8 k-pairs; the
// packed ratios live in a tiny smem table so only the 16 accumulator regs
// persist across the mainloop (register budget 64 -> occupancy 32 warps).
// ---------------------------------------------------------------------------
__global__ __launch_bounds__(256, 4)
void feat_kernel(const float* __restrict__ patch,
                 const float* __restrict__ qw,
                 float* __restrict__ out)
{
    const int bid   = blockIdx.x;
    const int bf    = bid & (NB*NF - 1);
    const int chunk = bid >> 9;
    const int f     = bf & (NF - 1);
    const int tid   = threadIdx.x;

    __shared__ __align__(16) float s_cl[YXC*NK];   // 4 KB
    __shared__ __align__(16) float s_r2[16];       // 8 packed (r,r') pairs
    __shared__ float s_red[8*NK];

    // Combined lat*lon table for this f, restricted to this chunk's yx range
    for (int i = tid; i < YXC*NK; i += 256) {
        int k   = i & 15;
        int yx  = chunk*YXC + (i >> 4);
        s_cl[i] = g_klat[(f*NK + k)*NY + (yx >> 4)] * g_klon[(f*NK + k)*NX + (yx & 15)];
    }
    if (tid < 16) s_r2[tid] = g_r[f*NK + tid];

    u64 acc[8];
    #pragma unroll
    for (int kp = 0; kp < 8; ++kp) acc[kp] = 0ull;
    __syncthreads();

    const float4* pbase = (const float4*)(patch + (size_t)bf * VOL)
                          + (size_t)chunk * (PTS*2);
    const float4* qbase = (const float4*)qw + (size_t)chunk * (PTS*2);
    const u64* r2s = (const u64*)s_r2;

    #pragma unroll 2
    for (int j = 0; j < JITER; ++j) {
        const int il = j*256 + tid;       // local point index within chunk
        float4 a0 = pbase[il*2];
        float4 a1 = pbase[il*2 + 1];
        float4 q0 = qbase[il*2];
        float4 q1 = qbase[il*2 + 1];

        float wp0 = a0.x*q0.x, wp1 = a0.y*q0.y, wp2 = a0.z*q0.z, wp3 = a0.w*q0.w;
        float wp4 = a1.x*q1.x, wp5 = a1.y*q1.y, wp6 = a1.z*q1.z, wp7 = a1.w*q1.w;
        u64 w[8];
        w[0] = pk2(wp0, wp0); w[1] = pk2(wp1, wp1);
        w[2] = pk2(wp2, wp2); w[3] = pk2(wp3, wp3);
        w[4] = pk2(wp4, wp4); w[5] = pk2(wp5, wp5);
        w[6] = pk2(wp6, wp6); w[7] = pk2(wp7, wp7);

        const u64* cl = (const u64*)(s_cl + (il >> 5) * NK);  // warp-uniform

        #pragma unroll
        for (int kp = 0; kp < 8; ++kp) {
            u64 r2 = r2s[kp];             // warp-uniform broadcast LDS.64
            u64 s = w[7];
            #pragma unroll
            for (int t = 6; t >= 0; --t) s = fma2(s, r2, w[t]);
            acc[kp] = fma2(s, cl[kp], acc[kp]);
        }
    }

    // Epilogue: apply klev (per-thread constant p), reduce 256 -> 1 per k,
    // scale by 1/integrated, atomically accumulate into out.
    const int p = tid & 31;
    float v[16];
    #pragma unroll
    for (int kp = 0; kp < 8; ++kp) {
        int k0 = f*NK + 2*kp;
        u64 kv2 = pk2(g_klev[k0*NP + p], g_klev[(k0+1)*NP + p]);
        float2 t2 = up2(mul2(acc[kp], kv2));
        v[2*kp]   = t2.x;
        v[2*kp+1] = t2.y;
    }
    #pragma unroll
    for (int kk = 0; kk < 16; ++kk) {
        #pragma unroll
        for (int o = 16; o; o >>= 1) v[kk] += __shfl_xor_sync(0xffffffffu, v[kk], o);
    }
    const int lane = tid & 31, wrp = tid >> 5;
    if (lane == 0) {
        #pragma unroll
        for (int kk = 0; kk < 16; ++kk) s_red[wrp*NK + kk] = v[kk];
    }
    __syncthreads();
    if (tid < NK) {
        float s = 0.f;
        #pragma unroll
        for (int w8 = 0; w8 < 8; ++w8) s += s_red[w8*NK + tid];
        const int fk = f*NK + tid;
        float integ = g_ipart[fk*4] + g_ipart[fk*4+1] + g_ipart[fk*4+2] + g_ipart[fk*4+3];
        atomicAdd(&out[(size_t)(bf >> 3) * (NF*NK) + fk],
                  s * (1.f / (integ + 1e-4f)));
    }
}

// ---------------------------------------------------------------------------
// Launch. Inputs (metadata order): patch, quadweights, mu_lat, logsigma_lat,
// mu_lon, logsigma_lon, mu_lev, logsigma_lev, logtau_time.
// ---------------------------------------------------------------------------
extern "C" void kernel_launch(void* const* d_in, const int* in_sizes, int n_in,
                              void* d_out, int out_size)
{
    (void)in_sizes; (void)n_in; (void)out_size;
    const float* patch  = (const float*)d_in[0];
    const float* qw     = (const float*)d_in[1];
    const float* mu_lat = (const float*)d_in[2];
    const float* ls_lat = (const float*)d_in[3];
    const float* mu_lon = (const float*)d_in[4];
    const float* ls_lon = (const float*)d_in[5];
    const float* mu_lev = (const float*)d_in[6];
    const float* ls_lev = (const float*)d_in[7];
    const float* lt     = (const float*)d_in[8];
    float* out = (float*)d_out;

    prep_kernel<<<NF*NK*4, 256>>>(qw, mu_lat, ls_lat, mu_lon, ls_lon,
                                  mu_lev, ls_lev, lt, out);
    feat_kernel<<<NB*NF*CHUNKS, 256>>>(patch, qw, out);
}